// round 6
// baseline (speedup 1.0000x reference)
#include <cuda_runtime.h>
#include <cstdint>

// Problem constants (fixed shapes for this problem)
#define NNODES 8192
#define KDIM   256     // in_embedding_len
#define MOUT   128     // out_embedding_len
#define EPSV   1e-5f
#define MASK_WORDS_PER_ROW (NNODES / 32)   // 256
#define MAX_DEG 2048

// Scratch (no cudaMalloc allowed): intermediates + adjacency bitmask
__device__ float    g_h1[NNODES * KDIM];
__device__ float    g_h2[NNODES * KDIM];
__device__ unsigned g_mask[NNODES * MASK_WORDS_PER_ROW];   // 8 MB

// ---------------- packed f32x2 helpers (Blackwell FFMA2 path) ----------------
__device__ __forceinline__ unsigned long long pk2(float lo, float hi) {
    unsigned long long r;
    asm("mov.b64 %0, {%1, %2};" : "=l"(r) : "f"(lo), "f"(hi));
    return r;
}
__device__ __forceinline__ void upk2(unsigned long long v, float& lo, float& hi) {
    asm("mov.b64 {%0, %1}, %2;" : "=f"(lo), "=f"(hi) : "l"(v));
}
__device__ __forceinline__ unsigned long long fma2(unsigned long long a,
                                                   unsigned long long b,
                                                   unsigned long long c) {
    unsigned long long d;
    asm("fma.rn.f32x2 %0, %1, %2, %3;" : "=l"(d) : "l"(a), "l"(b), "l"(c));
    return d;
}

// ---------------- fused GEMM + bias + LayerNorm (+tanh) ----------------
// out[row, :] = maybe_tanh( LN( X[row,:] @ W + bias ) * gam + bet )
// X: [NNODES, 256], W: [256, M], M in {256, 128}.
// One block = 32 rows x M cols; 256 threads; warp ty owns rows ty*4..ty*4+3,
// lane tx owns cols tx*CPT.. -> LayerNorm is a pure warp shfl reduce.
// BM=32 -> grid=256 (>148 SMs), regs capped for 2 CTAs/SM.
template <int M, bool DO_TANH>
__device__ __forceinline__
void gemm_ln_body(const float* __restrict__ X, const float* __restrict__ W,
                  const float* __restrict__ bias, const float* __restrict__ gam,
                  const float* __restrict__ bet, float* __restrict__ out)
{
    constexpr int K   = 256;
    constexpr int BM  = 32;
    constexpr int BK  = 32;
    constexpr int CPT = M / 32;      // cols per thread: 8 (M=256) or 4 (M=128)
    constexpr int CP2 = CPT / 2;     // packed f32x2 accumulators per row

    __shared__ __align__(16) float Xs[BK][BM + 4];  // stride 36 floats (144B = 9*16B)
    __shared__ __align__(16) float Ws[BK][M];

    const int t    = threadIdx.x;
    const int tx   = t & 31;
    const int ty   = t >> 5;             // 0..7
    const int row0 = blockIdx.x * BM;

    unsigned long long acc[4][CP2];
#pragma unroll
    for (int i = 0; i < 4; i++)
#pragma unroll
        for (int j = 0; j < CP2; j++) acc[i][j] = 0ull;

    for (int k0 = 0; k0 < K; k0 += BK) {
        // X tile 32x32, coalesced load, stored transposed
#pragma unroll
        for (int i = 0; i < (BM * BK) / 256; i++) {
            int l  = t + i * 256;
            int r  = l >> 5;
            int kk = l & 31;
            Xs[kk][r] = X[(row0 + r) * K + k0 + kk];
        }
        // W tile 32xM contiguous -> float4 copy
        {
            const float4* src = reinterpret_cast<const float4*>(W + k0 * M);
            float4*       dst = reinterpret_cast<float4*>(&Ws[0][0]);
#pragma unroll
            for (int i = 0; i < (BK * M) / (4 * 256); i++)
                dst[t + i * 256] = src[t + i * 256];
        }
        __syncthreads();

#pragma unroll
        for (int kk = 0; kk < BK; ++kk) {
            float4 a0 = *reinterpret_cast<const float4*>(&Xs[kk][ty * 4]);
            float av[4] = {a0.x, a0.y, a0.z, a0.w};
            unsigned long long bp[CP2];
#pragma unroll
            for (int j = 0; j < CP2; j += 2) {
                float4 b4 = *reinterpret_cast<const float4*>(&Ws[kk][tx * CPT + j * 2]);
                bp[j]     = pk2(b4.x, b4.y);
                bp[j + 1] = pk2(b4.z, b4.w);
            }
#pragma unroll
            for (int ri = 0; ri < 4; ri++) {
                unsigned long long aa = pk2(av[ri], av[ri]);
#pragma unroll
                for (int j = 0; j < CP2; j++) acc[ri][j] = fma2(aa, bp[j], acc[ri][j]);
            }
        }
        __syncthreads();
    }

    // Per-thread column params
    const int cbase = tx * CPT;
    float bs[CPT], gs[CPT], bes[CPT];
#pragma unroll
    for (int c = 0; c < CPT; c++) {
        bs[c]  = bias[cbase + c];
        gs[c]  = gam[cbase + c];
        bes[c] = bet[cbase + c];
    }

    // LayerNorm (+tanh) epilogue: warp ty reduces each of its 4 rows
#pragma unroll
    for (int ri = 0; ri < 4; ri++) {
        float v[CPT];
#pragma unroll
        for (int j = 0; j < CP2; j++) upk2(acc[ri][j], v[2 * j], v[2 * j + 1]);
        float s = 0.f, ss = 0.f;
#pragma unroll
        for (int c = 0; c < CPT; c++) {
            v[c] += bs[c];
            s  += v[c];
            ss += v[c] * v[c];
        }
#pragma unroll
        for (int o = 16; o > 0; o >>= 1) {
            s  += __shfl_xor_sync(0xffffffffu, s, o);
            ss += __shfl_xor_sync(0xffffffffu, ss, o);
        }
        const float mu   = s * (1.0f / M);
        const float var  = ss * (1.0f / M) - mu * mu;
        const float rstd = rsqrtf(var + EPSV);
        const int   row  = row0 + ty * 4 + ri;

        float ov[CPT];
#pragma unroll
        for (int c = 0; c < CPT; c++) {
            float o = (v[c] - mu) * rstd * gs[c] + bes[c];
            if (DO_TANH) o = tanhf(o);
            ov[c] = o;
        }
        float4* op = reinterpret_cast<float4*>(&out[row * M + cbase]);
#pragma unroll
        for (int j = 0; j < CPT / 4; j++)
            op[j] = make_float4(ov[4 * j], ov[4 * j + 1], ov[4 * j + 2], ov[4 * j + 3]);
    }
}

// Wrappers referencing device globals directly
__global__ __launch_bounds__(256, 2)
void gemm_ln_l1(const float* __restrict__ X, const float* __restrict__ W,
                const float* __restrict__ b, const float* __restrict__ g,
                const float* __restrict__ be)
{
    gemm_ln_body<256, true>(X, W, b, g, be, g_h1);
}
__global__ __launch_bounds__(256, 2)
void gemm_ln_l2(const float* __restrict__ W, const float* __restrict__ b,
                const float* __restrict__ g, const float* __restrict__ be)
{
    gemm_ln_body<256, true>(g_h1, W, b, g, be, g_h2);
}
__global__ __launch_bounds__(256, 2)
void gemm_ln_l3(const float* __restrict__ W, const float* __restrict__ b,
                const float* __restrict__ g, const float* __restrict__ be,
                float* __restrict__ emb)
{
    gemm_ln_body<128, false>(g_h2, W, b, g, be, emb);
}

// ---------------- adjacency bitmask ----------------
__global__ void zero_mask_kernel() {
    int i = blockIdx.x * blockDim.x + threadIdx.x;   // 2048*256 = 524288 uint4
    reinterpret_cast<uint4*>(g_mask)[i] = make_uint4(0u, 0u, 0u, 0u);
}

__global__ void set_edges_kernel(const int* __restrict__ ei, int E) {
    int e = blockIdx.x * blockDim.x + threadIdx.x;
    if (e >= E) return;
    int s = ei[e] - 1;         // 1-indexed input
    int d = ei[E + e] - 1;
    atomicOr(&g_mask[(unsigned)(s * NNODES + d) >> 5], 1u << (d & 31));
    atomicOr(&g_mask[(unsigned)(d * NNODES + s) >> 5], 1u << (s & 31));
}

// ---------------- sparse GAT row kernel (single-pass) ----------------
// One block per node i (128 threads = 4 warps).
//  1) scan the 256-word bitmask row -> compact neighbor list (dedup'd)
//  2) warp-per-neighbor: load emb_j ONCE (float4/lane), dot -> shfl-reduce ->
//     s=exp(d); accumulate den += s and oacc += s*emb_j in registers.
//  3) cross-warp combine in smem, normalize, write.
// NOTE: every smem array touched via float4 is explicitly 16B-aligned —
// nvcc only guarantees 4B alignment for float arrays (R4 misaligned-address bug).
__global__ __launch_bounds__(128)
void gat_row_kernel(const float* __restrict__ emb, float* __restrict__ xgat)
{
    const int i    = blockIdx.x;
    const int t    = threadIdx.x;
    const int lane = t & 31;
    const int wid  = t >> 5;

    __shared__ __align__(16) float ei_s[MOUT];
    __shared__ __align__(16) float wout[4][MOUT];
    __shared__ __align__(16) int   nbr[MAX_DEG];
    __shared__ float wden[4];
    __shared__ int   cnt;

    ei_s[t] = emb[i * MOUT + t];
    if (t == 0) cnt = 0;
    __syncthreads();

    // 1) compact the set bits of mask row i
    const unsigned* row = &g_mask[i * MASK_WORDS_PER_ROW];
#pragma unroll
    for (int w = t; w < MASK_WORDS_PER_ROW; w += 128) {
        unsigned m = row[w];
        while (m) {
            int b = __ffs(m) - 1;
            m &= m - 1;
            int p = atomicAdd(&cnt, 1);
            if (p < MAX_DEG) nbr[p] = w * 32 + b;
        }
    }
    __syncthreads();
    const int deg = cnt < MAX_DEG ? cnt : MAX_DEG;

    // 2) fused score + aggregate (warp per neighbor)
    const float4 ei4 = *reinterpret_cast<const float4*>(&ei_s[lane * 4]);
    float4 oac = make_float4(0.f, 0.f, 0.f, 0.f);
    float  dsum = 0.f;

    for (int n = wid; n < deg; n += 4) {
        const float4 ej4 = *reinterpret_cast<const float4*>(&emb[nbr[n] * MOUT + lane * 4]);
        float d = ej4.x * ei4.x + ej4.y * ei4.y + ej4.z * ei4.z + ej4.w * ei4.w;
#pragma unroll
        for (int o = 16; o > 0; o >>= 1) d += __shfl_xor_sync(0xffffffffu, d, o);
        const float s = expf(d);
        dsum  += s;
        oac.x += s * ej4.x;
        oac.y += s * ej4.y;
        oac.z += s * ej4.z;
        oac.w += s * ej4.w;
    }
    *reinterpret_cast<float4*>(&wout[wid][lane * 4]) = oac;
    if (lane == 0) wden[wid] = dsum;
    __syncthreads();

    // 3) cross-warp combine + normalize
    const float den  = wden[0] + wden[1] + wden[2] + wden[3];
    const float invd = den > 0.f ? 1.0f / den : 0.0f;
    const float tot  = wout[0][t] + wout[1][t] + wout[2][t] + wout[3][t];
    xgat[i * MOUT + t] = tot * invd;
}

// ---------------- launch ----------------
extern "C" void kernel_launch(void* const* d_in, const int* in_sizes, int n_in,
                              void* d_out, int out_size)
{
    const float* x   = (const float*)d_in[0];
    const int*   ei  = (const int*)d_in[1];
    const float* w1  = (const float*)d_in[2];
    const float* b1  = (const float*)d_in[3];
    const float* g1  = (const float*)d_in[4];
    const float* be1 = (const float*)d_in[5];
    const float* w2  = (const float*)d_in[6];
    const float* b2  = (const float*)d_in[7];
    const float* g2  = (const float*)d_in[8];
    const float* be2 = (const float*)d_in[9];
    const float* w3  = (const float*)d_in[10];
    const float* b3  = (const float*)d_in[11];
    const float* g3  = (const float*)d_in[12];
    const float* be3 = (const float*)d_in[13];

    float* out  = (float*)d_out;
    float* emb  = out;                     // [N, 128]
    float* xgat = out + NNODES * MOUT;     // [N, 128]

    const int E = in_sizes[1] / 2;

    // adjacency bitmask
    zero_mask_kernel<<<2048, 256>>>();
    set_edges_kernel<<<(E + 255) / 256, 256>>>(ei, E);

    // encoder
    gemm_ln_l1<<<NNODES / 32, 256>>>(x,  w1, b1, g1, be1);
    gemm_ln_l2<<<NNODES / 32, 256>>>(w2, b2, g2, be2);
    gemm_ln_l3<<<NNODES / 32, 256>>>(w3, b3, g3, be3, emb);

    // sparse GAT (fused single pass)
    gat_row_kernel<<<NNODES, 128>>>(emb, xgat);
}

// round 9
// speedup vs baseline: 1.3229x; 1.3229x over previous
#include <cuda_runtime.h>
#include <cstdint>

// Problem constants (fixed shapes for this problem)
#define NNODES 8192
#define KDIM   256     // in_embedding_len
#define MOUT   128     // out_embedding_len
#define EPSV   1e-5f
#define MASK_WORDS_PER_ROW (NNODES / 32)   // 256
#define MAX_DEG 2048

// Scratch (no cudaMalloc allowed): intermediates + adjacency bitmask
__device__ float    g_h1[NNODES * KDIM];
__device__ float    g_h2[NNODES * KDIM];
__device__ unsigned g_mask[NNODES * MASK_WORDS_PER_ROW];   // 8 MB

// ---------------- packed f32x2 helpers (Blackwell FFMA2 path) ----------------
__device__ __forceinline__ unsigned long long pk2(float lo, float hi) {
    unsigned long long r;
    asm("mov.b64 %0, {%1, %2};" : "=l"(r) : "f"(lo), "f"(hi));
    return r;
}
__device__ __forceinline__ void upk2(unsigned long long v, float& lo, float& hi) {
    asm("mov.b64 {%0, %1}, %2;" : "=f"(lo), "=f"(hi) : "l"(v));
}
__device__ __forceinline__ unsigned long long fma2(unsigned long long a,
                                                   unsigned long long b,
                                                   unsigned long long c) {
    unsigned long long d;
    asm("fma.rn.f32x2 %0, %1, %2, %3;" : "=l"(d) : "l"(a), "l"(b), "l"(c));
    return d;
}

// ---------------- cp.async helpers ----------------
__device__ __forceinline__ unsigned smem_u32(const void* p) {
    return (unsigned)__cvta_generic_to_shared(p);
}
__device__ __forceinline__ void cp16(unsigned dst, const void* src) {
    asm volatile("cp.async.ca.shared.global [%0], [%1], 16;" :: "r"(dst), "l"(src));
}
#define CP_COMMIT() asm volatile("cp.async.commit_group;")
#define CP_WAIT(N)  asm volatile("cp.async.wait_group %0;" :: "n"(N))

// ---------------- fused GEMM + bias + LayerNorm (+tanh) ----------------
// out[row,:] = maybe_tanh( LN( X[row,:] @ W + bias ) * gam + bet )
// X: [NNODES,256], W: [256,M], M in {256,128}.
// Block: 128 threads (4 warps), BM=32 rows -> grid=256 (covers 148 SMs).
// Warp w owns rows w*8..w*8+7; lane tx owns cols tx*CPT..+CPT-1
//  -> 8 x CPT per-thread tile: 8 FFMA2 per LDS.128,
//  -> LayerNorm = pure warp shfl reduce.
// K-chunks (BK=16) are cp.async double-buffered to overlap LDG with compute.
// Static smem: Xs 5.1KB + Ws 33.3KB = 38.4KB < 48KB static cap.
// W tile stored with even/odd col-group split (M=256) so the two per-lane
// float4 reads are smem-phase conflict-free.
template <int M, bool DO_TANH>
__device__ __forceinline__
void gemm_ln_body(const float* __restrict__ X, const float* __restrict__ W,
                  const float* __restrict__ bias, const float* __restrict__ gam,
                  const float* __restrict__ bet, float* __restrict__ out)
{
    constexpr int K    = 256;
    constexpr int BM   = 32;
    constexpr int BK   = 16;
    constexpr int CPT  = M / 32;     // 8 (M=256) or 4 (M=128)
    constexpr int CP2  = CPT / 2;    // packed accumulators per row
    constexpr int WST  = M + 4;      // Ws row stride in floats (16B-divisible)
    constexpr int NC4  = M / 4;      // float4 col-groups per W row

    __shared__ __align__(16) float Xs[2][BM][BK + 4];   // stride 20 floats
    __shared__ __align__(16) float Ws[2][BK][WST];

    const int t    = threadIdx.x;        // 0..127
    const int tx   = t & 31;
    const int wid  = t >> 5;             // 0..3
    const int w8   = wid * 8;
    const int row0 = blockIdx.x * BM;

    // ---- chunk loader (cp.async) ----
    auto load_chunk = [&](int c, int b) {
        const int k0 = c * BK;
        // X tile 32x16: 128 float4, 1 per thread
        {
            int r  = t >> 2;
            int c4 = t & 3;
            cp16(smem_u32(&Xs[b][r][c4 * 4]), X + (row0 + r) * K + k0 + c4 * 4);
        }
        // W tile 16xM from contiguous rows k0..k0+15
        const float* wsrc = W + k0 * M;
        constexpr int WF4 = (BK * M / 4) / 128;    // 8 (M=256) or 4 (M=128)
#pragma unroll
        for (int i = 0; i < WF4; i++) {
            int idx = t + i * 128;
            int kk  = idx / NC4;
            int c4  = idx % NC4;
            int p   = (CPT == 8) ? ((c4 & 1) * (M / 8) + (c4 >> 1)) : c4;
            cp16(smem_u32(&Ws[b][kk][p * 4]), wsrc + idx * 4);
        }
    };

    unsigned long long acc[8][CP2];
#pragma unroll
    for (int r = 0; r < 8; r++)
#pragma unroll
        for (int j = 0; j < CP2; j++) acc[r][j] = 0ull;

    load_chunk(0, 0);
    CP_COMMIT();

    int buf = 0;
#pragma unroll 1
    for (int c = 0; c < K / BK; c++) {
        if (c + 1 < K / BK) {
            load_chunk(c + 1, buf ^ 1);
            CP_COMMIT();
            CP_WAIT(1);              // chunk c complete; c+1 in flight
        } else {
            CP_WAIT(0);
        }
        __syncthreads();

        // compute on buf: 4 groups of 4 kk
#pragma unroll
        for (int g = 0; g < BK / 4; g++) {
            float4 xv[8];
#pragma unroll
            for (int r = 0; r < 8; r++)
                xv[r] = *reinterpret_cast<const float4*>(&Xs[buf][w8 + r][g * 4]);
#pragma unroll
            for (int q = 0; q < 4; q++) {
                const int kk = g * 4 + q;
                const float* wr = &Ws[buf][kk][0];
                unsigned long long bp[CP2];
                {
                    float4 w0 = *reinterpret_cast<const float4*>(&wr[tx * 4]);
                    bp[0] = pk2(w0.x, w0.y);
                    bp[1] = pk2(w0.z, w0.w);
                    if (CPT == 8) {
                        float4 w1 = *reinterpret_cast<const float4*>(&wr[(M / 8 + tx) * 4]);
                        bp[2] = pk2(w1.x, w1.y);
                        bp[3] = pk2(w1.z, w1.w);
                    }
                }
#pragma unroll
                for (int r = 0; r < 8; r++) {
                    float a = (q == 0) ? xv[r].x : (q == 1) ? xv[r].y
                            : (q == 2) ? xv[r].z : xv[r].w;
                    unsigned long long aa = pk2(a, a);
#pragma unroll
                    for (int j = 0; j < CP2; j++)
                        acc[r][j] = fma2(aa, bp[j], acc[r][j]);
                }
            }
        }
        __syncthreads();
        buf ^= 1;
    }

    // ---- epilogue: bias + LayerNorm (+tanh), warp-shfl reduction per row ----
    const int cbase = tx * CPT;
    float bs[CPT], gs[CPT], bes[CPT];
#pragma unroll
    for (int c = 0; c < CPT; c++) {
        bs[c]  = bias[cbase + c];
        gs[c]  = gam[cbase + c];
        bes[c] = bet[cbase + c];
    }

#pragma unroll
    for (int r = 0; r < 8; r++) {
        float v[CPT];
#pragma unroll
        for (int j = 0; j < CP2; j++) upk2(acc[r][j], v[2 * j], v[2 * j + 1]);
        float s = 0.f, ss = 0.f;
#pragma unroll
        for (int c = 0; c < CPT; c++) {
            v[c] += bs[c];
            s  += v[c];
            ss += v[c] * v[c];
        }
#pragma unroll
        for (int o = 16; o > 0; o >>= 1) {
            s  += __shfl_xor_sync(0xffffffffu, s, o);
            ss += __shfl_xor_sync(0xffffffffu, ss, o);
        }
        const float mu   = s * (1.0f / M);
        const float var  = ss * (1.0f / M) - mu * mu;
        const float rstd = rsqrtf(var + EPSV);
        const int   row  = row0 + w8 + r;

        float ov[CPT];
#pragma unroll
        for (int c = 0; c < CPT; c++) {
            float o = (v[c] - mu) * rstd * gs[c] + bes[c];
            if (DO_TANH) o = tanhf(o);
            ov[c] = o;
        }
        float4* op = reinterpret_cast<float4*>(&out[row * M + cbase]);
#pragma unroll
        for (int j = 0; j < CPT / 4; j++)
            op[j] = make_float4(ov[4 * j], ov[4 * j + 1], ov[4 * j + 2], ov[4 * j + 3]);
    }
}

// Wrappers referencing device globals directly
__global__ __launch_bounds__(128, 2)
void gemm_ln_l1(const float* __restrict__ X, const float* __restrict__ W,
                const float* __restrict__ b, const float* __restrict__ g,
                const float* __restrict__ be)
{
    gemm_ln_body<256, true>(X, W, b, g, be, g_h1);
}
__global__ __launch_bounds__(128, 2)
void gemm_ln_l2(const float* __restrict__ W, const float* __restrict__ b,
                const float* __restrict__ g, const float* __restrict__ be)
{
    gemm_ln_body<256, true>(g_h1, W, b, g, be, g_h2);
}
__global__ __launch_bounds__(128, 2)
void gemm_ln_l3(const float* __restrict__ W, const float* __restrict__ b,
                const float* __restrict__ g, const float* __restrict__ be,
                float* __restrict__ emb)
{
    gemm_ln_body<128, false>(g_h2, W, b, g, be, emb);
}

// ---------------- adjacency bitmask ----------------
__global__ void zero_mask_kernel() {
    int i = blockIdx.x * blockDim.x + threadIdx.x;   // 2048*256 = 524288 uint4
    reinterpret_cast<uint4*>(g_mask)[i] = make_uint4(0u, 0u, 0u, 0u);
}

__global__ void set_edges_kernel(const int* __restrict__ ei, int E) {
    int e = blockIdx.x * blockDim.x + threadIdx.x;
    if (e >= E) return;
    int s = ei[e] - 1;         // 1-indexed input
    int d = ei[E + e] - 1;
    atomicOr(&g_mask[(unsigned)(s * NNODES + d) >> 5], 1u << (d & 31));
    atomicOr(&g_mask[(unsigned)(d * NNODES + s) >> 5], 1u << (s & 31));
}

// ---------------- sparse GAT row kernel (single-pass) ----------------
// One block per node i (128 threads = 4 warps).
//  1) scan the 256-word bitmask row -> compact neighbor list (dedup'd)
//  2) warp-per-neighbor: load emb_j ONCE (float4/lane), dot -> shfl-reduce ->
//     s=exp(d); accumulate den += s and oacc += s*emb_j in registers.
//  3) cross-warp combine in smem, normalize, write.
// All smem arrays touched via float4 are explicitly 16B-aligned.
__global__ __launch_bounds__(128)
void gat_row_kernel(const float* __restrict__ emb, float* __restrict__ xgat)
{
    const int i    = blockIdx.x;
    const int t    = threadIdx.x;
    const int lane = t & 31;
    const int wid  = t >> 5;

    __shared__ __align__(16) float ei_s[MOUT];
    __shared__ __align__(16) float wout[4][MOUT];
    __shared__ __align__(16) int   nbr[MAX_DEG];
    __shared__ float wden[4];
    __shared__ int   cnt;

    ei_s[t] = emb[i * MOUT + t];
    if (t == 0) cnt = 0;
    __syncthreads();

    // 1) compact the set bits of mask row i
    const unsigned* row = &g_mask[i * MASK_WORDS_PER_ROW];
#pragma unroll
    for (int w = t; w < MASK_WORDS_PER_ROW; w += 128) {
        unsigned m = row[w];
        while (m) {
            int b = __ffs(m) - 1;
            m &= m - 1;
            int p = atomicAdd(&cnt, 1);
            if (p < MAX_DEG) nbr[p] = w * 32 + b;
        }
    }
    __syncthreads();
    const int deg = cnt < MAX_DEG ? cnt : MAX_DEG;

    // 2) fused score + aggregate (warp per neighbor)
    const float4 ei4 = *reinterpret_cast<const float4*>(&ei_s[lane * 4]);
    float4 oac = make_float4(0.f, 0.f, 0.f, 0.f);
    float  dsum = 0.f;

    for (int n = wid; n < deg; n += 4) {
        const float4 ej4 = *reinterpret_cast<const float4*>(&emb[nbr[n] * MOUT + lane * 4]);
        float d = ej4.x * ei4.x + ej4.y * ei4.y + ej4.z * ei4.z + ej4.w * ei4.w;
#pragma unroll
        for (int o = 16; o > 0; o >>= 1) d += __shfl_xor_sync(0xffffffffu, d, o);
        const float s = expf(d);
        dsum  += s;
        oac.x += s * ej4.x;
        oac.y += s * ej4.y;
        oac.z += s * ej4.z;
        oac.w += s * ej4.w;
    }
    *reinterpret_cast<float4*>(&wout[wid][lane * 4]) = oac;
    if (lane == 0) wden[wid] = dsum;
    __syncthreads();

    // 3) cross-warp combine + normalize
    const float den  = wden[0] + wden[1] + wden[2] + wden[3];
    const float invd = den > 0.f ? 1.0f / den : 0.0f;
    const float tot  = wout[0][t] + wout[1][t] + wout[2][t] + wout[3][t];
    xgat[i * MOUT + t] = tot * invd;
}

// ---------------- launch ----------------
extern "C" void kernel_launch(void* const* d_in, const int* in_sizes, int n_in,
                              void* d_out, int out_size)
{
    const float* x   = (const float*)d_in[0];
    const int*   ei  = (const int*)d_in[1];
    const float* w1  = (const float*)d_in[2];
    const float* b1  = (const float*)d_in[3];
    const float* g1  = (const float*)d_in[4];
    const float* be1 = (const float*)d_in[5];
    const float* w2  = (const float*)d_in[6];
    const float* b2  = (const float*)d_in[7];
    const float* g2  = (const float*)d_in[8];
    const float* be2 = (const float*)d_in[9];
    const float* w3  = (const float*)d_in[10];
    const float* b3  = (const float*)d_in[11];
    const float* g3  = (const float*)d_in[12];
    const float* be3 = (const float*)d_in[13];

    float* out  = (float*)d_out;
    float* emb  = out;                     // [N, 128]
    float* xgat = out + NNODES * MOUT;     // [N, 128]

    const int E = in_sizes[1] / 2;

    // adjacency bitmask
    zero_mask_kernel<<<2048, 256>>>();
    set_edges_kernel<<<(E + 255) / 256, 256>>>(ei, E);

    // encoder
    gemm_ln_l1<<<NNODES / 32, 128>>>(x,  w1, b1, g1, be1);
    gemm_ln_l2<<<NNODES / 32, 128>>>(w2, b2, g2, be2);
    gemm_ln_l3<<<NNODES / 32, 128>>>(w3, b3, g3, be3, emb);

    // sparse GAT (fused single pass)
    gat_row_kernel<<<NNODES, 128>>>(emb, xgat);
}